// round 15
// baseline (speedup 1.0000x reference)
#include <cuda_runtime.h>
#include <math.h>

#define NB 256
#define NT 32
#define CODE_NUM 4880
#define MED_NUM 1000
#define CS 128
#define HD 128
#define OUTN 4880
#define NROWS (NB*NT)      // 8192
#define R3 (3*HD)          // 384

// ---------------- scratch (static, allocation-free) ----------------
__device__ float g_Hc[CODE_NUM*HD];      // tanh(c_emb @ W_c)
__device__ float g_Hm[MED_NUM*HD];       // tanh(m_emb @ W_m)
__device__ float g_repre[(long long)NROWS*R3];
__device__ float g_scores[NROWS];
__device__ float g_ctx[NB*R3];

// ==================== 1. embedding transform ====================
// rows 0..4879 -> Hc, rows 4880..5879 -> Hm. 8 rows per block, 128 threads.
__global__ __launch_bounds__(128, 8)
void transform_kernel(const float* __restrict__ c_emb,
                      const float* __restrict__ m_emb,
                      const float* __restrict__ W_c,
                      const float* __restrict__ W_m) {
    __shared__ float s_emb[8][CS];
    const int tid = threadIdx.x;
    const int row0 = blockIdx.x * 8;
    const bool is_med = row0 >= CODE_NUM;
    const float* emb = is_med ? m_emb : c_emb;
    const float* W   = is_med ? W_m : W_c;
    float* dst       = is_med ? g_Hm : g_Hc;
    const int nrows  = is_med ? MED_NUM : CODE_NUM;
    const int base   = is_med ? (row0 - CODE_NUM) : row0;

    #pragma unroll
    for (int r = 0; r < 8; r++) {
        int rr = base + r;
        s_emb[r][tid] = (rr < nrows) ? emb[rr*CS + tid] : 0.0f;
    }
    __syncthreads();

    float a[8];
    #pragma unroll
    for (int r = 0; r < 8; r++) a[r] = 0.f;
    #pragma unroll 4
    for (int k = 0; k < CS; k++) {
        float w = W[k*HD + tid];
        #pragma unroll
        for (int r = 0; r < 8; r++)
            a[r] = fmaf(s_emb[r][k], w, a[r]);
    }
    #pragma unroll
    for (int r = 0; r < 8; r++)
        if (base + r < nrows) dst[(base+r)*HD + tid] = tanhf(a[r]);
}

// ==================== 2. visit aggregation + attention scores ====================
__device__ __forceinline__ float4 f4add(float4 a, float4 b) {
    a.x += b.x; a.y += b.y; a.z += b.z; a.w += b.w; return a;
}

__global__ __launch_bounds__(128, 8)
void visit_kernel(const float* __restrict__ code_x,
                  const float* __restrict__ med_x,
                  const float* __restrict__ Wa,
                  const float* __restrict__ ba,
                  const float* __restrict__ va) {
    __shared__ int s_idx[CODE_NUM];                     // 19.5 KB: worst-case nnz list
    __shared__ int s_wsum[4];
    __shared__ __align__(16) float s_part[4][HD];       // per-warp partial sums
    __shared__ float s_rep[R3];

    const int tid  = threadIdx.x;   // 128 threads
    const int lane = tid & 31;
    const int wid  = tid >> 5;
    const int row  = blockIdx.x;    // (b,t) flattened

    // ---------------- diagnosis codes ----------------
    const float* cx = code_x + (long long)row * CODE_NUM;
    unsigned long long bits = 0;
    {   // pass 1: nonzero bitmap (float4 loads; <=10 iters, 40 bits)
        int it = 0;
        for (int i0 = tid * 4; i0 < CODE_NUM; i0 += 512, it++) {
            float4 v = *reinterpret_cast<const float4*>(cx + i0);
            unsigned m = (unsigned)(v.x != 0.f)
                       | ((unsigned)(v.y != 0.f) << 1)
                       | ((unsigned)(v.z != 0.f) << 2)
                       | ((unsigned)(v.w != 0.f) << 3);
            bits |= (unsigned long long)m << (it * 4);
        }
    }
    int local = __popcll(bits);
    int incl = local;
    #pragma unroll
    for (int o = 1; o < 32; o <<= 1) {
        int n = __shfl_up_sync(0xffffffffu, incl, o);
        if (lane >= o) incl += n;
    }
    if (lane == 31) s_wsum[wid] = incl;
    __syncthreads();
    int total_c = s_wsum[0] + s_wsum[1] + s_wsum[2] + s_wsum[3];
    {
        int wbase = 0;
        if (wid > 0) wbase += s_wsum[0];
        if (wid > 1) wbase += s_wsum[1];
        if (wid > 2) wbase += s_wsum[2];
        int p = wbase + incl - local;
        int it = 0;
        for (int i0 = tid * 4; i0 < CODE_NUM; i0 += 512, it++) {
            unsigned m = (unsigned)(bits >> (it * 4)) & 0xFu;
            if (m & 1u) s_idx[p++] = i0;
            if (m & 2u) s_idx[p++] = i0 + 1;
            if (m & 4u) s_idx[p++] = i0 + 2;
            if (m & 8u) s_idx[p++] = i0 + 3;
        }
    }
    __syncthreads();

    // gather: warp w takes a fixed quarter of the list (deterministic order)
    {
        int chunk = (total_c + 3) >> 2;
        int j0 = wid * chunk;
        int j1 = min(j0 + chunk, total_c);
        float4 a0 = make_float4(0.f,0.f,0.f,0.f), a1 = a0, a2 = a0, a3 = a0;
        int j = j0;
        for (; j + 4 <= j1; j += 4) {
            int i0 = s_idx[j], i1 = s_idx[j+1], i2 = s_idx[j+2], i3 = s_idx[j+3];
            a0 = f4add(a0, *reinterpret_cast<const float4*>(g_Hc + i0*HD + lane*4));
            a1 = f4add(a1, *reinterpret_cast<const float4*>(g_Hc + i1*HD + lane*4));
            a2 = f4add(a2, *reinterpret_cast<const float4*>(g_Hc + i2*HD + lane*4));
            a3 = f4add(a3, *reinterpret_cast<const float4*>(g_Hc + i3*HD + lane*4));
        }
        for (; j < j1; j++)
            a0 = f4add(a0, *reinterpret_cast<const float4*>(g_Hc + s_idx[j]*HD + lane*4));
        float4 t = f4add(f4add(a0, a1), f4add(a2, a3));
        *reinterpret_cast<float4*>(&s_part[wid][lane*4]) = t;
    }
    __syncthreads();
    float h_c = (s_part[0][tid] + s_part[1][tid]) + (s_part[2][tid] + s_part[3][tid]);
    h_c *= 1.0f / fmaxf((float)total_c, 1.0f);
    __syncthreads();   // everyone done reading s_part / s_idx before med phase reuses them

    // ---------------- medicine codes ----------------
    const float* mx = med_x + (long long)row * MED_NUM;
    bits = 0;
    {   // 1000/128 -> 8 iters
        int it = 0;
        for (int i = tid; i < MED_NUM; i += 128, it++)
            if (mx[i] != 0.0f) bits |= 1ull << it;
    }
    local = __popcll(bits);
    incl = local;
    #pragma unroll
    for (int o = 1; o < 32; o <<= 1) {
        int n = __shfl_up_sync(0xffffffffu, incl, o);
        if (lane >= o) incl += n;
    }
    if (lane == 31) s_wsum[wid] = incl;
    __syncthreads();
    int total_m = s_wsum[0] + s_wsum[1] + s_wsum[2] + s_wsum[3];
    {
        int wbase = 0;
        if (wid > 0) wbase += s_wsum[0];
        if (wid > 1) wbase += s_wsum[1];
        if (wid > 2) wbase += s_wsum[2];
        int p = wbase + incl - local;
        int it = 0;
        for (int i = tid; i < MED_NUM; i += 128, it++)
            if ((bits >> it) & 1ull) s_idx[p++] = i;
    }
    __syncthreads();
    {
        int chunk = (total_m + 3) >> 2;
        int j0 = wid * chunk;
        int j1 = min(j0 + chunk, total_m);
        float4 a0 = make_float4(0.f,0.f,0.f,0.f), a1 = a0;
        int j = j0;
        for (; j + 2 <= j1; j += 2) {
            int i0 = s_idx[j], i1 = s_idx[j+1];
            a0 = f4add(a0, *reinterpret_cast<const float4*>(g_Hm + i0*HD + lane*4));
            a1 = f4add(a1, *reinterpret_cast<const float4*>(g_Hm + i1*HD + lane*4));
        }
        for (; j < j1; j++)
            a0 = f4add(a0, *reinterpret_cast<const float4*>(g_Hm + s_idx[j]*HD + lane*4));
        float4 t = f4add(a0, a1);
        *reinterpret_cast<float4*>(&s_part[wid][lane*4]) = t;
    }
    __syncthreads();
    float h_m = (s_part[0][tid] + s_part[1][tid]) + (s_part[2][tid] + s_part[3][tid]);
    h_m *= 1.0f / fmaxf((float)total_m, 1.0f);

    // ---------------- repre + attention score ----------------
    float prod = h_c * h_m;
    float* rp = g_repre + (long long)row * R3;
    rp[tid]        = h_c;
    rp[HD + tid]   = h_m;
    rp[2*HD + tid] = prod;
    s_rep[tid]        = h_c;
    s_rep[HD + tid]   = h_m;
    s_rep[2*HD + tid] = prod;
    __syncthreads();

    if (wid == 0) {
        float a = ba[lane];
        #pragma unroll 8
        for (int k = 0; k < R3; k++)
            a = fmaf(s_rep[k], Wa[k*32 + lane], a);
        float t = tanhf(a) * va[lane];
        #pragma unroll
        for (int o = 16; o; o >>= 1)
            t += __shfl_xor_sync(0xffffffffu, t, o);
        if (lane == 0) g_scores[row] = t;
    }
}

// ==================== 3. masked softmax over T + context ====================
__global__ __launch_bounds__(384, 4)
void attn_kernel(const int* __restrict__ lens) {
    __shared__ float s_attn[NT];
    const int b = blockIdx.x;
    const int tid = threadIdx.x;   // 384 threads

    if (tid < 32) {
        int len = lens[b];
        float s = (tid < len) ? g_scores[b*NT + tid] : -1e9f;
        float m = s;
        #pragma unroll
        for (int o = 16; o; o >>= 1) m = fmaxf(m, __shfl_xor_sync(0xffffffffu, m, o));
        float e = expf(s - m);                 // masked lanes underflow to exactly 0
        float sum = e;
        #pragma unroll
        for (int o = 16; o; o >>= 1) sum += __shfl_xor_sync(0xffffffffu, sum, o);
        s_attn[tid] = e / sum;
    }
    __syncthreads();

    float acc = 0.f;
    #pragma unroll
    for (int t = 0; t < NT; t++)
        acc = fmaf(s_attn[t], g_repre[((long long)(b*NT + t))*R3 + tid], acc);
    g_ctx[b*R3 + tid] = acc;
}

// ==================== 4. classifier: sigmoid(ctx @ W_cls + b) ====================
// 64(M) x 128(N) block tile, 8x4 per-thread micro-tile, BK=32, 256 threads.
__global__ __launch_bounds__(256, 2)
void cls_kernel(const float* __restrict__ Wc,
                const float* __restrict__ bc,
                float* __restrict__ out) {
    __shared__ __align__(16) float sA[32][72];    // [k][m], padded
    __shared__ __align__(16) float sB[32][128];   // [k][n]
    const int tid = threadIdx.x;                  // 256 threads
    const int n0 = blockIdx.x * 128;
    const int m0 = blockIdx.y * 64;
    const int tn = (tid & 31) * 4;                // 0..124
    const int tm = (tid >> 5) * 8;                // 0..56

    float acc[8][4];
    #pragma unroll
    for (int i = 0; i < 8; i++)
        #pragma unroll
        for (int j = 0; j < 4; j++) acc[i][j] = 0.f;

    for (int k0 = 0; k0 < R3; k0 += 32) {
        int e = tid;
        #pragma unroll
        for (int r = 0; r < 8; r++, e += 256) {      // A tile 64x32
            int k = e & 31, m = e >> 5;
            sA[k][m] = g_ctx[(m0 + m)*R3 + k0 + k];
        }
        e = tid;
        #pragma unroll
        for (int r = 0; r < 16; r++, e += 256) {     // B tile 32x128
            int n = e & 127, k = e >> 7;
            int col = n0 + n;
            sB[k][n] = (col < OUTN) ? Wc[(long long)(k0 + k)*OUTN + col] : 0.f;
        }
        __syncthreads();

        #pragma unroll
        for (int kk = 0; kk < 32; kk++) {
            float4 b4 = *reinterpret_cast<const float4*>(&sB[kk][tn]);
            float4 a4lo = *reinterpret_cast<const float4*>(&sA[kk][tm]);
            float4 a4hi = *reinterpret_cast<const float4*>(&sA[kk][tm+4]);
            float av[8] = { a4lo.x, a4lo.y, a4lo.z, a4lo.w,
                            a4hi.x, a4hi.y, a4hi.z, a4hi.w };
            float bv[4] = { b4.x, b4.y, b4.z, b4.w };
            #pragma unroll
            for (int i = 0; i < 8; i++)
                #pragma unroll
                for (int j = 0; j < 4; j++)
                    acc[i][j] = fmaf(av[i], bv[j], acc[i][j]);
        }
        __syncthreads();
    }

    #pragma unroll
    for (int i = 0; i < 8; i++) {
        int m = m0 + tm + i;
        #pragma unroll
        for (int j = 0; j < 4; j++) {
            int n = n0 + tn + j;
            if (n < OUTN) {
                float z = acc[i][j] + bc[n];
                out[(long long)m*OUTN + n] = 1.0f / (1.0f + expf(-z));
            }
        }
    }
}

// ==================== launch ====================
extern "C" void kernel_launch(void* const* d_in, const int* in_sizes, int n_in,
                              void* d_out, int out_size) {
    const float* code_x = (const float*)d_in[0];
    // d_in[1] = divided, d_in[2] = neighbors: dead inputs, never read
    const int*   lens   = (const int*)  d_in[3];
    const float* med    = (const float*)d_in[4];
    const float* c_emb  = (const float*)d_in[5];
    const float* m_emb  = (const float*)d_in[6];
    const float* W_c    = (const float*)d_in[7];
    const float* W_m    = (const float*)d_in[8];
    const float* W_a    = (const float*)d_in[9];
    const float* ba     = (const float*)d_in[10];
    const float* va     = (const float*)d_in[11];
    const float* W_cls  = (const float*)d_in[12];
    const float* b_cls  = (const float*)d_in[13];
    float* out = (float*)d_out;

    transform_kernel<<<(CODE_NUM + MED_NUM + 7) / 8, 128>>>(c_emb, m_emb, W_c, W_m);
    visit_kernel<<<NROWS, 128>>>(code_x, med, W_a, ba, va);
    attn_kernel<<<NB, 384>>>(lens);
    cls_kernel<<<dim3((OUTN + 127) / 128, NB / 64), 256>>>(W_cls, b_cls, out);
}

// round 17
// speedup vs baseline: 1.0931x; 1.0931x over previous
#include <cuda_runtime.h>
#include <cuda_fp16.h>
#include <math.h>

#define NB 256
#define NT 32
#define CODE_NUM 4880
#define MED_NUM 1000
#define CS 128
#define HD 128
#define OUTN 4880
#define NROWS (NB*NT)      // 8192
#define R3 (3*HD)          // 384

// ---------------- scratch (static, allocation-free) ----------------
__device__ __align__(256) __half g_Hch[CODE_NUM*HD];  // tanh(c_emb @ W_c), fp16
__device__ float g_Hm[MED_NUM*HD];                    // tanh(m_emb @ W_m), fp32
__device__ float g_repre[(long long)NROWS*R3];
__device__ float g_scores[NROWS];
__device__ float g_ctx[NB*R3];

// ==================== 1. embedding transform ====================
// rows 0..4879 -> Hch (fp16), rows 4880..5879 -> Hm (fp32). 8 rows/block, 128 thr.
__global__ __launch_bounds__(128, 8)
void transform_kernel(const float* __restrict__ c_emb,
                      const float* __restrict__ m_emb,
                      const float* __restrict__ W_c,
                      const float* __restrict__ W_m) {
    __shared__ float s_emb[8][CS];
    const int tid = threadIdx.x;
    const int row0 = blockIdx.x * 8;
    const bool is_med = row0 >= CODE_NUM;
    const float* emb = is_med ? m_emb : c_emb;
    const float* W   = is_med ? W_m : W_c;
    const int nrows  = is_med ? MED_NUM : CODE_NUM;
    const int base   = is_med ? (row0 - CODE_NUM) : row0;

    #pragma unroll
    for (int r = 0; r < 8; r++) {
        int rr = base + r;
        s_emb[r][tid] = (rr < nrows) ? emb[rr*CS + tid] : 0.0f;
    }
    __syncthreads();

    float a[8];
    #pragma unroll
    for (int r = 0; r < 8; r++) a[r] = 0.f;
    #pragma unroll 4
    for (int k = 0; k < CS; k++) {
        float w = W[k*HD + tid];
        #pragma unroll
        for (int r = 0; r < 8; r++)
            a[r] = fmaf(s_emb[r][k], w, a[r]);
    }
    #pragma unroll
    for (int r = 0; r < 8; r++) {
        if (base + r < nrows) {
            float t = tanhf(a[r]);
            if (is_med) g_Hm[(base+r)*HD + tid] = t;
            else        g_Hch[(base+r)*HD + tid] = __float2half(t);
        }
    }
}

// ==================== 2. visit aggregation + attention scores ====================
__device__ __forceinline__ float4 f4add(float4 a, float4 b) {
    a.x += b.x; a.y += b.y; a.z += b.z; a.w += b.w; return a;
}
// add 8 packed halves (as uint4) into 8 fp32 accumulators
__device__ __forceinline__ void addh8(float* acc, uint4 r) {
    float2 p;
    p = __half22float2(*reinterpret_cast<__half2*>(&r.x)); acc[0]+=p.x; acc[1]+=p.y;
    p = __half22float2(*reinterpret_cast<__half2*>(&r.y)); acc[2]+=p.x; acc[3]+=p.y;
    p = __half22float2(*reinterpret_cast<__half2*>(&r.z)); acc[4]+=p.x; acc[5]+=p.y;
    p = __half22float2(*reinterpret_cast<__half2*>(&r.w)); acc[6]+=p.x; acc[7]+=p.y;
}

__global__ __launch_bounds__(128, 8)
void visit_kernel(const float* __restrict__ code_x,
                  const float* __restrict__ med_x,
                  const float* __restrict__ Wa,
                  const float* __restrict__ ba,
                  const float* __restrict__ va) {
    __shared__ int s_idx[CODE_NUM];                     // 19.5 KB worst-case nnz list
    __shared__ int s_wsum[4];
    __shared__ __align__(16) float s_part[4][HD];       // per-warp partial sums
    __shared__ float s_rep[R3];

    const int tid  = threadIdx.x;   // 128 threads
    const int lane = tid & 31;
    const int wid  = tid >> 5;
    const int row  = blockIdx.x;    // (b,t) flattened

    // ---------------- diagnosis codes: bitmap + scan + compact ----------------
    const float* cx = code_x + (long long)row * CODE_NUM;
    unsigned long long bits = 0;
    {
        int it = 0;
        for (int i0 = tid * 4; i0 < CODE_NUM; i0 += 512, it++) {
            float4 v = *reinterpret_cast<const float4*>(cx + i0);
            unsigned m = (unsigned)(v.x != 0.f)
                       | ((unsigned)(v.y != 0.f) << 1)
                       | ((unsigned)(v.z != 0.f) << 2)
                       | ((unsigned)(v.w != 0.f) << 3);
            bits |= (unsigned long long)m << (it * 4);
        }
    }
    int local = __popcll(bits);
    int incl = local;
    #pragma unroll
    for (int o = 1; o < 32; o <<= 1) {
        int n = __shfl_up_sync(0xffffffffu, incl, o);
        if (lane >= o) incl += n;
    }
    if (lane == 31) s_wsum[wid] = incl;
    __syncthreads();
    int total_c = s_wsum[0] + s_wsum[1] + s_wsum[2] + s_wsum[3];
    {
        int wbase = 0;
        if (wid > 0) wbase += s_wsum[0];
        if (wid > 1) wbase += s_wsum[1];
        if (wid > 2) wbase += s_wsum[2];
        int p = wbase + incl - local;
        int it = 0;
        for (int i0 = tid * 4; i0 < CODE_NUM; i0 += 512, it++) {
            unsigned m = (unsigned)(bits >> (it * 4)) & 0xFu;
            if (m & 1u) s_idx[p++] = i0;
            if (m & 2u) s_idx[p++] = i0 + 1;
            if (m & 4u) s_idx[p++] = i0 + 2;
            if (m & 8u) s_idx[p++] = i0 + 3;
        }
    }
    __syncthreads();

    // gather (fp16 Hc, 2 codes per warp-load): warp w takes a fixed quarter
    {
        int chunk = (total_c + 3) >> 2;
        int j0 = wid * chunk;
        int j1 = min(j0 + chunk, total_c);
        const int half = lane >> 4;      // 0: even code of pair, 1: odd
        const int hl   = lane & 15;      // dim group: dims [hl*8, hl*8+8)
        float acc[8];
        #pragma unroll
        for (int d = 0; d < 8; d++) acc[d] = 0.f;

        int j = j0;
        for (; j + 8 <= j1; j += 8) {    // 4 loads in flight per lane
            int i0 = s_idx[j     + half];
            int i1 = s_idx[j + 2 + half];
            int i2 = s_idx[j + 4 + half];
            int i3 = s_idx[j + 6 + half];
            uint4 r0 = *reinterpret_cast<const uint4*>(g_Hch + i0*HD + hl*8);
            uint4 r1 = *reinterpret_cast<const uint4*>(g_Hch + i1*HD + hl*8);
            uint4 r2 = *reinterpret_cast<const uint4*>(g_Hch + i2*HD + hl*8);
            uint4 r3 = *reinterpret_cast<const uint4*>(g_Hch + i3*HD + hl*8);
            addh8(acc, r0); addh8(acc, r1); addh8(acc, r2); addh8(acc, r3);
        }
        for (; j + 2 <= j1; j += 2) {
            int i0 = s_idx[j + half];
            uint4 r0 = *reinterpret_cast<const uint4*>(g_Hch + i0*HD + hl*8);
            addh8(acc, r0);
        }
        if (j < j1 && half == 0) {       // single leftover code
            int i0 = s_idx[j];
            uint4 r0 = *reinterpret_cast<const uint4*>(g_Hch + i0*HD + hl*8);
            addh8(acc, r0);
        }
        // combine the two half-warps (same dims, different codes)
        #pragma unroll
        for (int d = 0; d < 8; d++)
            acc[d] += __shfl_down_sync(0xffffffffu, acc[d], 16);
        if (half == 0) {
            *reinterpret_cast<float4*>(&s_part[wid][hl*8])     = make_float4(acc[0], acc[1], acc[2], acc[3]);
            *reinterpret_cast<float4*>(&s_part[wid][hl*8 + 4]) = make_float4(acc[4], acc[5], acc[6], acc[7]);
        }
    }
    __syncthreads();
    float h_c = (s_part[0][tid] + s_part[1][tid]) + (s_part[2][tid] + s_part[3][tid]);
    h_c *= 1.0f / fmaxf((float)total_c, 1.0f);
    __syncthreads();   // s_part / s_idx reused by med phase

    // ---------------- medicine codes (fp32 Hm, unchanged) ----------------
    const float* mx = med_x + (long long)row * MED_NUM;
    bits = 0;
    {
        int it = 0;
        for (int i = tid; i < MED_NUM; i += 128, it++)
            if (mx[i] != 0.0f) bits |= 1ull << it;
    }
    local = __popcll(bits);
    incl = local;
    #pragma unroll
    for (int o = 1; o < 32; o <<= 1) {
        int n = __shfl_up_sync(0xffffffffu, incl, o);
        if (lane >= o) incl += n;
    }
    if (lane == 31) s_wsum[wid] = incl;
    __syncthreads();
    int total_m = s_wsum[0] + s_wsum[1] + s_wsum[2] + s_wsum[3];
    {
        int wbase = 0;
        if (wid > 0) wbase += s_wsum[0];
        if (wid > 1) wbase += s_wsum[1];
        if (wid > 2) wbase += s_wsum[2];
        int p = wbase + incl - local;
        int it = 0;
        for (int i = tid; i < MED_NUM; i += 128, it++)
            if ((bits >> it) & 1ull) s_idx[p++] = i;
    }
    __syncthreads();
    {
        int chunk = (total_m + 3) >> 2;
        int j0 = wid * chunk;
        int j1 = min(j0 + chunk, total_m);
        float4 a0 = make_float4(0.f,0.f,0.f,0.f), a1 = a0;
        int j = j0;
        for (; j + 2 <= j1; j += 2) {
            int i0 = s_idx[j], i1 = s_idx[j+1];
            a0 = f4add(a0, *reinterpret_cast<const float4*>(g_Hm + i0*HD + lane*4));
            a1 = f4add(a1, *reinterpret_cast<const float4*>(g_Hm + i1*HD + lane*4));
        }
        for (; j < j1; j++)
            a0 = f4add(a0, *reinterpret_cast<const float4*>(g_Hm + s_idx[j]*HD + lane*4));
        float4 t = f4add(a0, a1);
        *reinterpret_cast<float4*>(&s_part[wid][lane*4]) = t;
    }
    __syncthreads();
    float h_m = (s_part[0][tid] + s_part[1][tid]) + (s_part[2][tid] + s_part[3][tid]);
    h_m *= 1.0f / fmaxf((float)total_m, 1.0f);

    // ---------------- repre + attention score ----------------
    float prod = h_c * h_m;
    float* rp = g_repre + (long long)row * R3;
    rp[tid]        = h_c;
    rp[HD + tid]   = h_m;
    rp[2*HD + tid] = prod;
    s_rep[tid]        = h_c;
    s_rep[HD + tid]   = h_m;
    s_rep[2*HD + tid] = prod;
    __syncthreads();

    if (wid == 0) {
        float a = ba[lane];
        #pragma unroll 8
        for (int k = 0; k < R3; k++)
            a = fmaf(s_rep[k], Wa[k*32 + lane], a);
        float t = tanhf(a) * va[lane];
        #pragma unroll
        for (int o = 16; o; o >>= 1)
            t += __shfl_xor_sync(0xffffffffu, t, o);
        if (lane == 0) g_scores[row] = t;
    }
}

// ==================== 3. masked softmax over T + context ====================
__global__ __launch_bounds__(384, 4)
void attn_kernel(const int* __restrict__ lens) {
    __shared__ float s_attn[NT];
    const int b = blockIdx.x;
    const int tid = threadIdx.x;   // 384 threads

    if (tid < 32) {
        int len = lens[b];
        float s = (tid < len) ? g_scores[b*NT + tid] : -1e9f;
        float m = s;
        #pragma unroll
        for (int o = 16; o; o >>= 1) m = fmaxf(m, __shfl_xor_sync(0xffffffffu, m, o));
        float e = expf(s - m);
        float sum = e;
        #pragma unroll
        for (int o = 16; o; o >>= 1) sum += __shfl_xor_sync(0xffffffffu, sum, o);
        s_attn[tid] = e / sum;
    }
    __syncthreads();

    float acc = 0.f;
    #pragma unroll
    for (int t = 0; t < NT; t++)
        acc = fmaf(s_attn[t], g_repre[((long long)(b*NT + t))*R3 + tid], acc);
    g_ctx[b*R3 + tid] = acc;
}

// ==================== 4. classifier: sigmoid(ctx @ W_cls + b) ====================
// 32(M) x 128(N) tile, 4x4 micro, BK=32, 256 threads. 312 blocks -> ~4 CTAs/SM.
__global__ __launch_bounds__(256, 4)
void cls_kernel(const float* __restrict__ Wc,
                const float* __restrict__ bc,
                float* __restrict__ out) {
    __shared__ __align__(16) float sA[32][36];    // [k][m], padded
    __shared__ __align__(16) float sB[32][128];   // [k][n]
    const int tid = threadIdx.x;                  // 256 threads
    const int n0 = blockIdx.x * 128;
    const int m0 = blockIdx.y * 32;
    const int tn = (tid & 31) * 4;                // 0..124
    const int tm = (tid >> 5) * 4;                // 0..28

    float acc[4][4];
    #pragma unroll
    for (int i = 0; i < 4; i++)
        #pragma unroll
        for (int j = 0; j < 4; j++) acc[i][j] = 0.f;

    for (int k0 = 0; k0 < R3; k0 += 32) {
        int e = tid;
        #pragma unroll
        for (int r = 0; r < 4; r++, e += 256) {      // A tile 32x32
            int k = e & 31, m = e >> 5;
            sA[k][m] = g_ctx[(m0 + m)*R3 + k0 + k];
        }
        e = tid;
        #pragma unroll
        for (int r = 0; r < 16; r++, e += 256) {     // B tile 32x128
            int n = e & 127, k = e >> 7;
            int col = n0 + n;
            sB[k][n] = (col < OUTN) ? Wc[(long long)(k0 + k)*OUTN + col] : 0.f;
        }
        __syncthreads();

        #pragma unroll
        for (int kk = 0; kk < 32; kk++) {
            float4 b4 = *reinterpret_cast<const float4*>(&sB[kk][tn]);
            float4 a4 = *reinterpret_cast<const float4*>(&sA[kk][tm]);
            float av[4] = { a4.x, a4.y, a4.z, a4.w };
            float bv[4] = { b4.x, b4.y, b4.z, b4.w };
            #pragma unroll
            for (int i = 0; i < 4; i++)
                #pragma unroll
                for (int j = 0; j < 4; j++)
                    acc[i][j] = fmaf(av[i], bv[j], acc[i][j]);
        }
        __syncthreads();
    }

    #pragma unroll
    for (int i = 0; i < 4; i++) {
        int m = m0 + tm + i;
        #pragma unroll
        for (int j = 0; j < 4; j++) {
            int n = n0 + tn + j;
            if (n < OUTN) {
                float z = acc[i][j] + bc[n];
                out[(long long)m*OUTN + n] = 1.0f / (1.0f + expf(-z));
            }
        }
    }
}

// ==================== launch ====================
extern "C" void kernel_launch(void* const* d_in, const int* in_sizes, int n_in,
                              void* d_out, int out_size) {
    const float* code_x = (const float*)d_in[0];
    // d_in[1] = divided, d_in[2] = neighbors: dead inputs, never read
    const int*   lens   = (const int*)  d_in[3];
    const float* med    = (const float*)d_in[4];
    const float* c_emb  = (const float*)d_in[5];
    const float* m_emb  = (const float*)d_in[6];
    const float* W_c    = (const float*)d_in[7];
    const float* W_m    = (const float*)d_in[8];
    const float* W_a    = (const float*)d_in[9];
    const float* ba     = (const float*)d_in[10];
    const float* va     = (const float*)d_in[11];
    const float* W_cls  = (const float*)d_in[12];
    const float* b_cls  = (const float*)d_in[13];
    float* out = (float*)d_out;

    transform_kernel<<<(CODE_NUM + MED_NUM + 7) / 8, 128>>>(c_emb, m_emb, W_c, W_m);
    visit_kernel<<<NROWS, 128>>>(code_x, med, W_a, ba, va);
    attn_kernel<<<NB, 384>>>(lens);
    cls_kernel<<<dim3((OUTN + 127) / 128, NB / 32), 256>>>(W_cls, b_cls, out);
}